// round 3
// baseline (speedup 1.0000x reference)
#include <cuda_runtime.h>
#include <math.h>

// Shapes (fixed)
#define BN   2048
#define NN   256
#define DIN  128
#define DE   64
#define HH   128
#define MD   1664

typedef unsigned long long ull;

// Scratch
__device__ float g_hi[BN * DIN];
__device__ float g_hj[BN * DIN];
__device__ float g_m[(size_t)BN * MD];
__device__ float g_WihT[DIN * 3 * HH];   // [k][384]
__device__ float g_WhhT[DIN * 3 * HH];

// ---- f32x2 helpers --------------------------------------------------------
__device__ __forceinline__ ull ffma2(ull a, ull b, ull c) {
    ull d;
    asm("fma.rn.f32x2 %0, %1, %2, %3;" : "=l"(d) : "l"(a), "l"(b), "l"(c));
    return d;
}
__device__ __forceinline__ ull pk(float a, float b) {
    ull d; asm("mov.b64 %0, {%1,%2};" : "=l"(d) : "f"(a), "f"(b)); return d;
}
__device__ __forceinline__ ull dup(float a) {
    ull d; asm("mov.b64 %0, {%1,%1};" : "=l"(d) : "f"(a)); return d;
}
__device__ __forceinline__ void unpk(ull v, float& x, float& y) {
    asm("mov.b64 {%0,%1}, %2;" : "=f"(x), "=f"(y) : "l"(v));
}

// ---------------------------------------------------------------------------
// K0: transpose GRU weights to k-major [k][384]
// ---------------------------------------------------------------------------
__global__ void k0_prep(const float* __restrict__ Wih,
                        const float* __restrict__ Whh) {
    int idx = blockIdx.x * 128 + threadIdx.x;
    if (idx < 384 * 128) {
        int r = idx >> 7, c = idx & 127;
        g_WihT[c * 384 + r] = Wih[idx];
        g_WhhT[c * 384 + r] = Whh[idx];
    }
}

// ---------------------------------------------------------------------------
// K1: hi/hj projections + copy input into g_m[:,0:128]
// ---------------------------------------------------------------------------
__global__ void __launch_bounds__(128) k1_hij(const float* __restrict__ input,
                                              const float* __restrict__ preW) {
    __shared__ float As[16 * 128];
    int t = threadIdx.x;
    int n0 = blockIdx.x * 16;

    for (int s = t; s < 16 * 128; s += 128) {
        float v = input[(size_t)n0 * 128 + s];
        As[s] = v;
        g_m[(size_t)(n0 + (s >> 7)) * MD + (s & 127)] = v;
    }
    __syncthreads();

    float hi[16], hj[16];
#pragma unroll
    for (int r = 0; r < 16; r++) { hi[r] = 0.f; hj[r] = 0.f; }

    for (int e = 0; e < 128; e += 4) {
        float wi0 = preW[(e + 0) * 128 + t];
        float wi1 = preW[(e + 1) * 128 + t];
        float wi2 = preW[(e + 2) * 128 + t];
        float wi3 = preW[(e + 3) * 128 + t];
        float wj0 = preW[(128 + e + 0) * 128 + t];
        float wj1 = preW[(128 + e + 1) * 128 + t];
        float wj2 = preW[(128 + e + 2) * 128 + t];
        float wj3 = preW[(128 + e + 3) * 128 + t];
#pragma unroll
        for (int r = 0; r < 16; r++) {
            const float4 a = *(const float4*)&As[r * 128 + e];
            hi[r] += a.x * wi0 + a.y * wi1 + a.z * wi2 + a.w * wi3;
            hj[r] += a.x * wj0 + a.y * wj1 + a.z * wj2 + a.w * wj3;
        }
    }
#pragma unroll
    for (int r = 0; r < 16; r++) {
        g_hi[(size_t)(n0 + r) * 128 + t] = hi[r];
        g_hj[(size_t)(n0 + r) * 128 + t] = hj[r];
    }
}

// ---------------------------------------------------------------------------
// K2: per-node sparse aggregation (unchanged)
// ---------------------------------------------------------------------------
__global__ void __launch_bounds__(128) k2_agg(const float* __restrict__ adj,
                                              const float* __restrict__ adjf,
                                              const float* __restrict__ preW,
                                              const float* __restrict__ preb) {
    __shared__ float WeS[DE * 128];
    __shared__ float efT[DE * 4];
    __shared__ int   nbr[NN];
    __shared__ int   cnt;

    int t = threadIdx.x;
    int node = blockIdx.x;
    int nbase = (node >> 8) << 8;

    for (int s = t; s < DE * 128; s += 128) WeS[s] = preW[256 * 128 + s];
    if (t == 0) cnt = 0;
    __syncthreads();

    const float* arow = adj + (size_t)node * NN;
    for (int j = t; j < NN; j += 128)
        if (arow[j] > 0.0f) { int p = atomicAdd(&cnt, 1); nbr[p] = j; }
    __syncthreads();

    int deg = cnt;
    float base = g_hi[(size_t)node * 128 + t] + preb[t];
    float s1 = 0.f, s2 = 0.f, mx = -1e30f, mn = 1e30f;
    const float* efb = adjf + (size_t)node * NN * DE;

    for (int p0 = 0; p0 < deg; p0 += 4) {
        int nb = deg - p0; if (nb > 4) nb = 4;
        __syncthreads();
        for (int s = t; s < DE * 4; s += 128) {
            int u = s & 3, e = s >> 2;
            efT[s] = (u < nb) ? efb[(size_t)nbr[p0 + u] * DE + e] : 0.0f;
        }
        __syncthreads();

        float hjv[4];
#pragma unroll
        for (int u = 0; u < 4; u++) {
            int uu = (u < nb) ? u : 0;
            hjv[u] = g_hj[(size_t)(nbase + nbr[p0 + uu]) * 128 + t];
        }

        float e0 = 0.f, e1 = 0.f, e2 = 0.f, e3 = 0.f;
#pragma unroll
        for (int e = 0; e < DE; e++) {
            float w = WeS[e * 128 + t];
            const float4 v = *(const float4*)&efT[e * 4];
            e0 += v.x * w; e1 += v.y * w; e2 += v.z * w; e3 += v.w * w;
        }
        float ev[4] = {e0, e1, e2, e3};
#pragma unroll
        for (int u = 0; u < 4; u++) {
            if (p0 + u < deg) {
                float tv = base + hjv[u] + ev[u];
                s1 += tv; s2 += tv * tv;
                mx = fmaxf(mx, tv); mn = fminf(mn, tv);
            }
        }
    }

    float degf = (float)deg;
    float degc = fmaxf(degf, 1e-5f);
    float mean = s1 / degc;
    float var = s2 / degc - mean * mean;
    if (var < 0.f) var = 0.f;
    float sd = sqrtf(var + 1e-5f);
    float mxo = (deg > 0) ? mx : 0.f;
    float mno = (deg > 0) ? mn : 0.f;
    float slog = logf(degf + 1.0f) / 3.3f;
    float inv = 1.0f / (slog + 1e-5f);

    float* mrow = g_m + (size_t)node * MD;
    mrow[ 128 + t] = mean;        mrow[ 256 + t] = mxo;
    mrow[ 384 + t] = mno;         mrow[ 512 + t] = sd;
    mrow[ 640 + t] = mean * slog; mrow[ 768 + t] = mxo * slog;
    mrow[ 896 + t] = mno * slog;  mrow[1024 + t] = sd * slog;
    mrow[1152 + t] = mean * inv;  mrow[1280 + t] = mxo * inv;
    mrow[1408 + t] = mno * inv;   mrow[1536 + t] = sd * inv;
}

// ---------------------------------------------------------------------------
// K3 v3: col-pair f32x2, plain (non-duplicated) smem, k-split into 2 groups.
// Block: 512 threads, 16 rows x 128 cols. Group g = tid>>8 handles half of k.
// Within group: thread = 1 row x 8 cols (4 f32x2 col-pair accumulators).
// ---------------------------------------------------------------------------
#define KT1  32
#define NT1  26       // 26*32 = 832 = half of MD
#define KTG  8
#define NTG  8        // 8*8 = 64 = half of 128

// smem (floats):
//  [0, 16384)   WBUF (64KB): weight tiles / partial buffers (time-multiplexed)
//  [16384,+1024) As: group g at +g*512, layout [row][32]
//  [17408,+2048) Ys [row][128]
//  [19456,+2048) Xs [row][128]
//  [21504,+2048) Hs [row][128]
#define SMEM_F  23552
#define SMEM_K3 (SMEM_F * 4)

__global__ void __launch_bounds__(512, 1) k3_tail(
        const float* __restrict__ postW, const float* __restrict__ postb,
        const float* __restrict__ mixW,  const float* __restrict__ mixb,
        const float* __restrict__ hidden, float* __restrict__ out) {
    extern __shared__ float sm[];
    float* WBUF = sm;
    float* As   = sm + 16384;
    float* Ys   = sm + 17408;
    float* Xs   = sm + 19456;
    float* Hs   = sm + 21504;

    const int tid  = threadIdx.x;
    const int g    = tid >> 8;       // k-group 0/1
    const int r    = tid & 255;
    const int row  = r >> 4;         // 0..15
    const int col8 = (r & 15) * 8;   // 0,8,...,120
    const int n0   = blockIdx.x * 16;

    float* Wg = WBUF + g * 8192;
    float* Ag = As + g * 512;

    // ---- stage hidden [row][128] (flat, conflict-free) ----
#pragma unroll
    for (int j = 0; j < 4; j++) {
        int idx = tid + j * 512;
        Hs[idx] = hidden[(size_t)n0 * 128 + idx];
    }

    // ======================= phase 1: y1 = m_cat @ post_W ==================
    const float4* pw4 = (const float4*)postW;
    const int kbase0 = g * (NT1 * KT1);    // 0 or 832

    float4 wreg[4];
    float  areg[2];
#pragma unroll
    for (int j = 0; j < 4; j++) wreg[j] = pw4[kbase0 * 32 + r * 4 + j];
#pragma unroll
    for (int j = 0; j < 2; j++) {
        int idx = r + j * 256;
        areg[j] = g_m[(size_t)(n0 + (idx >> 5)) * MD + kbase0 + (idx & 31)];
    }

    ull acc0 = 0, acc1 = 0, acc2 = 0, acc3 = 0;
    for (int tile = 0; tile < NT1; tile++) {
        if (tile) __syncthreads();
#pragma unroll
        for (int j = 0; j < 4; j++) ((float4*)Wg)[r * 4 + j] = wreg[j];
#pragma unroll
        for (int j = 0; j < 2; j++) Ag[r + j * 256] = areg[j];
        __syncthreads();
        if (tile + 1 < NT1) {
            int kb = kbase0 + (tile + 1) * KT1;
#pragma unroll
            for (int j = 0; j < 4; j++) wreg[j] = pw4[kb * 32 + r * 4 + j];
#pragma unroll
            for (int j = 0; j < 2; j++) {
                int idx = r + j * 256;
                areg[j] = g_m[(size_t)(n0 + (idx >> 5)) * MD + kb + (idx & 31)];
            }
        }
#pragma unroll
        for (int kk = 0; kk < KT1; kk++) {
            ull a2 = dup(Ag[row * 32 + kk]);
            float4 w0 = *(const float4*)&Wg[kk * 128 + col8];
            float4 w1 = *(const float4*)&Wg[kk * 128 + col8 + 4];
            acc0 = ffma2(a2, pk(w0.x, w0.y), acc0);
            acc1 = ffma2(a2, pk(w0.z, w0.w), acc1);
            acc2 = ffma2(a2, pk(w1.x, w1.y), acc2);
            acc3 = ffma2(a2, pk(w1.z, w1.w), acc3);
        }
    }

    // prefetch mixW group slice (32KB/group) while reducing
    float4 mreg[8];
#pragma unroll
    for (int j = 0; j < 8; j++) mreg[j] = ((const float4*)mixW)[g * 2048 + r * 8 + j];

    // ---- reduce partials across groups, add bias -> Ys ----
    __syncthreads();                       // WBUF free, all compute done
    float* Ypart = WBUF;                   // 2048 floats
    if (g == 1) {
        float x0, x1, x2, x3, x4, x5, x6, x7;
        unpk(acc0, x0, x1); unpk(acc1, x2, x3); unpk(acc2, x4, x5); unpk(acc3, x6, x7);
        *(float4*)&Ypart[row * 128 + col8]     = make_float4(x0, x1, x2, x3);
        *(float4*)&Ypart[row * 128 + col8 + 4] = make_float4(x4, x5, x6, x7);
    }
    __syncthreads();
    if (g == 0) {
        float x[8];
        unpk(acc0, x[0], x[1]); unpk(acc1, x[2], x[3]);
        unpk(acc2, x[4], x[5]); unpk(acc3, x[6], x[7]);
        float4 p0 = *(const float4*)&Ypart[row * 128 + col8];
        float4 p1 = *(const float4*)&Ypart[row * 128 + col8 + 4];
        float pp[8] = {p0.x, p0.y, p0.z, p0.w, p1.x, p1.y, p1.z, p1.w};
#pragma unroll
        for (int i = 0; i < 8; i++) x[i] += pp[i] + postb[col8 + i];
        *(float4*)&Ys[row * 128 + col8]     = make_float4(x[0], x[1], x[2], x[3]);
        *(float4*)&Ys[row * 128 + col8 + 4] = make_float4(x[4], x[5], x[6], x[7]);
    }
    __syncthreads();

    // ======================= phase 2: mix + leaky ==========================
#pragma unroll
    for (int j = 0; j < 8; j++) ((float4*)Wg)[r * 8 + j] = mreg[j];
    __syncthreads();

    ull m0 = 0, m1 = 0, m2 = 0, m3 = 0;
    {
        const int kb = g * 64;
#pragma unroll 8
        for (int kk = 0; kk < 64; kk++) {
            ull a2 = dup(Ys[row * 128 + kb + kk]);
            float4 w0 = *(const float4*)&Wg[kk * 128 + col8];
            float4 w1 = *(const float4*)&Wg[kk * 128 + col8 + 4];
            m0 = ffma2(a2, pk(w0.x, w0.y), m0);
            m1 = ffma2(a2, pk(w0.z, w0.w), m1);
            m2 = ffma2(a2, pk(w1.x, w1.y), m2);
            m3 = ffma2(a2, pk(w1.z, w1.w), m3);
        }
    }
    __syncthreads();
    float* Mpart = WBUF;
    if (g == 1) {
        float x0, x1, x2, x3, x4, x5, x6, x7;
        unpk(m0, x0, x1); unpk(m1, x2, x3); unpk(m2, x4, x5); unpk(m3, x6, x7);
        *(float4*)&Mpart[row * 128 + col8]     = make_float4(x0, x1, x2, x3);
        *(float4*)&Mpart[row * 128 + col8 + 4] = make_float4(x4, x5, x6, x7);
    }
    __syncthreads();
    if (g == 0) {
        float x[8];
        unpk(m0, x[0], x[1]); unpk(m1, x[2], x[3]);
        unpk(m2, x[4], x[5]); unpk(m3, x[6], x[7]);
        float4 p0 = *(const float4*)&Mpart[row * 128 + col8];
        float4 p1 = *(const float4*)&Mpart[row * 128 + col8 + 4];
        float pp[8] = {p0.x, p0.y, p0.z, p0.w, p1.x, p1.y, p1.z, p1.w};
#pragma unroll
        for (int i = 0; i < 8; i++) {
            float y = x[i] + pp[i] + mixb[col8 + i];
            x[i] = (y > 0.f) ? y : 0.01f * y;
        }
        *(float4*)&Xs[row * 128 + col8]     = make_float4(x[0], x[1], x[2], x[3]);
        *(float4*)&Xs[row * 128 + col8 + 4] = make_float4(x[4], x[5], x[6], x[7]);
    }

    // ======================= phase 3: GRU ==================================
    const float4* wiT4 = (const float4*)g_WihT;
    const float4* whT4 = (const float4*)g_WhhT;
    const int kgb = g * 64;

    float4 gi[3], gh[3];
#pragma unroll
    for (int j = 0; j < 3; j++) {
        gi[j] = wiT4[kgb * 96 + r * 3 + j];
        gh[j] = whT4[kgb * 96 + r * 3 + j];
    }

    ull R0=0,R1=0,R2=0,R3=0, Z0=0,Z1=0,Z2=0,Z3=0;
    ull I0=0,I1=0,I2=0,I3=0, H0=0,H1=0,H2=0,H3=0;

    float* WiS = WBUF + g * 8192;          // 3072 floats
    float* WhS = WiS + 3072;

    for (int tg = 0; tg < NTG; tg++) {
        __syncthreads();                   // prev readers done / Xs ready (tg==0)
#pragma unroll
        for (int j = 0; j < 3; j++) {
            ((float4*)WiS)[r * 3 + j] = gi[j];
            ((float4*)WhS)[r * 3 + j] = gh[j];
        }
        __syncthreads();
        if (tg + 1 < NTG) {
            int kb = (kgb + (tg + 1) * KTG) * 96;
#pragma unroll
            for (int j = 0; j < 3; j++) {
                gi[j] = wiT4[kb + r * 3 + j];
                gh[j] = whT4[kb + r * 3 + j];
            }
        }
#pragma unroll
        for (int kk = 0; kk < KTG; kk++) {
            int k = kgb + tg * KTG + kk;
            ull x2 = dup(Xs[row * 128 + k]);
            ull h2 = dup(Hs[row * 128 + k]);
            int b = kk * 384;
            float4 wr0 = *(const float4*)&WiS[b + col8];
            float4 wr1 = *(const float4*)&WiS[b + col8 + 4];
            float4 wz0 = *(const float4*)&WiS[b + 128 + col8];
            float4 wz1 = *(const float4*)&WiS[b + 128 + col8 + 4];
            float4 wn0 = *(const float4*)&WiS[b + 256 + col8];
            float4 wn1 = *(const float4*)&WiS[b + 256 + col8 + 4];
            float4 vr0 = *(const float4*)&WhS[b + col8];
            float4 vr1 = *(const float4*)&WhS[b + col8 + 4];
            float4 vz0 = *(const float4*)&WhS[b + 128 + col8];
            float4 vz1 = *(const float4*)&WhS[b + 128 + col8 + 4];
            float4 vn0 = *(const float4*)&WhS[b + 256 + col8];
            float4 vn1 = *(const float4*)&WhS[b + 256 + col8 + 4];
            R0 = ffma2(x2, pk(wr0.x, wr0.y), R0); R0 = ffma2(h2, pk(vr0.x, vr0.y), R0);
            R1 = ffma2(x2, pk(wr0.z, wr0.w), R1); R1 = ffma2(h2, pk(vr0.z, vr0.w), R1);
            R2 = ffma2(x2, pk(wr1.x, wr1.y), R2); R2 = ffma2(h2, pk(vr1.x, vr1.y), R2);
            R3 = ffma2(x2, pk(wr1.z, wr1.w), R3); R3 = ffma2(h2, pk(vr1.z, vr1.w), R3);
            Z0 = ffma2(x2, pk(wz0.x, wz0.y), Z0); Z0 = ffma2(h2, pk(vz0.x, vz0.y), Z0);
            Z1 = ffma2(x2, pk(wz0.z, wz0.w), Z1); Z1 = ffma2(h2, pk(vz0.z, vz0.w), Z1);
            Z2 = ffma2(x2, pk(wz1.x, wz1.y), Z2); Z2 = ffma2(h2, pk(vz1.x, vz1.y), Z2);
            Z3 = ffma2(x2, pk(wz1.z, wz1.w), Z3); Z3 = ffma2(h2, pk(vz1.z, vz1.w), Z3);
            I0 = ffma2(x2, pk(wn0.x, wn0.y), I0);
            I1 = ffma2(x2, pk(wn0.z, wn0.w), I1);
            I2 = ffma2(x2, pk(wn1.x, wn1.y), I2);
            I3 = ffma2(x2, pk(wn1.z, wn1.w), I3);
            H0 = ffma2(h2, pk(vn0.x, vn0.y), H0);
            H1 = ffma2(h2, pk(vn0.z, vn0.w), H1);
            H2 = ffma2(h2, pk(vn1.x, vn1.y), H2);
            H3 = ffma2(h2, pk(vn1.z, vn1.w), H3);
        }
    }

    // ---- cross-group gate reduction + epilogue ----
    __syncthreads();
    float* Gp = WBUF;                       // 4 x 2048 floats (32KB)
    if (g == 1) {
        ull rr[4] = {R0, R1, R2, R3};
        ull zz[4] = {Z0, Z1, Z2, Z3};
        ull ii[4] = {I0, I1, I2, I3};
        ull hh[4] = {H0, H1, H2, H3};
#pragma unroll
        for (int p = 0; p < 4; p++) {
            float a, b;
            unpk(rr[p], a, b); *(float2*)&Gp[          row * 128 + col8 + 2 * p] = make_float2(a, b);
            unpk(zz[p], a, b); *(float2*)&Gp[2048 +    row * 128 + col8 + 2 * p] = make_float2(a, b);
            unpk(ii[p], a, b); *(float2*)&Gp[4096 +    row * 128 + col8 + 2 * p] = make_float2(a, b);
            unpk(hh[p], a, b); *(float2*)&Gp[6144 +    row * 128 + col8 + 2 * p] = make_float2(a, b);
        }
    }
    __syncthreads();
    if (g == 0) {
        float Rv[8], Zv[8], Iv[8], Hv[8];
        unpk(R0, Rv[0], Rv[1]); unpk(R1, Rv[2], Rv[3]); unpk(R2, Rv[4], Rv[5]); unpk(R3, Rv[6], Rv[7]);
        unpk(Z0, Zv[0], Zv[1]); unpk(Z1, Zv[2], Zv[3]); unpk(Z2, Zv[4], Zv[5]); unpk(Z3, Zv[6], Zv[7]);
        unpk(I0, Iv[0], Iv[1]); unpk(I1, Iv[2], Iv[3]); unpk(I2, Iv[4], Iv[5]); unpk(I3, Iv[6], Iv[7]);
        unpk(H0, Hv[0], Hv[1]); unpk(H1, Hv[2], Hv[3]); unpk(H2, Hv[4], Hv[5]); unpk(H3, Hv[6], Hv[7]);
        float o[8];
#pragma unroll
        for (int i = 0; i < 8; i++) {
            int c = col8 + i;
            float rg = Rv[i] + Gp[row * 128 + c];
            float zg = Zv[i] + Gp[2048 + row * 128 + c];
            float ig = Iv[i] + Gp[4096 + row * 128 + c];
            float hg = Hv[i] + Gp[6144 + row * 128 + c];
            float rs = 1.0f / (1.0f + expf(-rg));
            float zs = 1.0f / (1.0f + expf(-zg));
            float nn = tanhf(ig + rs * hg);
            float hv = Hs[row * 128 + c];
            o[i] = (1.0f - zs) * nn + zs * hv;
        }
        *(float4*)&out[(size_t)(n0 + row) * 128 + col8]     = make_float4(o[0], o[1], o[2], o[3]);
        *(float4*)&out[(size_t)(n0 + row) * 128 + col8 + 4] = make_float4(o[4], o[5], o[6], o[7]);
    }
}

// ---------------------------------------------------------------------------
extern "C" void kernel_launch(void* const* d_in, const int* in_sizes, int n_in,
                              void* d_out, int out_size) {
    const float* input  = (const float*)d_in[0];
    const float* adj    = (const float*)d_in[1];
    const float* adjf   = (const float*)d_in[2];
    const float* hidden = (const float*)d_in[3];
    const float* preW   = (const float*)d_in[4];
    const float* preb   = (const float*)d_in[5];
    const float* postW  = (const float*)d_in[6];
    const float* postb  = (const float*)d_in[7];
    const float* mixW   = (const float*)d_in[8];
    const float* mixb   = (const float*)d_in[9];
    const float* Wih    = (const float*)d_in[10];
    const float* Whh    = (const float*)d_in[11];
    float* out = (float*)d_out;

    cudaFuncSetAttribute(k3_tail, cudaFuncAttributeMaxDynamicSharedMemorySize, SMEM_K3);

    k0_prep<<<384, 128>>>(Wih, Whh);
    k1_hij<<<128, 128>>>(input, preW);
    k2_agg<<<BN, 128>>>(adj, adjf, preW, preb);
    k3_tail<<<128, 512, SMEM_K3>>>(postW, postb, mixW, mixb, hidden, out);
}